// round 13
// baseline (speedup 1.0000x reference)
#include <cuda_runtime.h>
#include <cstdint>
#include <cstddef>

#define TT 512
#define BATCH 512
#define HH 128
#define G3 384

// ---------------- scratch (static __device__, no allocation) ----------------
__device__ float g_y0[(size_t)TT * BATCH * 256];            // layer0 output [t][b][256] (fwd|bwd), tf32-rounded
__device__ float g_xp1[2][(size_t)TT * BATCH * G3];         // layer1 input projections per dir
__device__ float g_hcat[(size_t)BATCH * 256];               // final hiddens [b][256] (fwd|bwd)
__device__ float g_wtf[2][G3 * 256];                        // tf32-rounded layer1 w_ih per dir

// ---------------- helpers ----------------
__device__ __forceinline__ unsigned long long pack2(float x) {
    unsigned long long r;
    asm("mov.b64 %0, {%1, %1};" : "=l"(r) : "f"(x));
    return r;
}
__device__ __forceinline__ unsigned long long f2fma(unsigned long long a, unsigned long long b,
                                                    unsigned long long c) {
    unsigned long long d;
    asm("fma.rn.f32x2 %0, %1, %2, %3;" : "=l"(d) : "l"(a), "l"(b), "l"(c));
    return d;
}
__device__ __forceinline__ float sigf(float x) {
    float e = __expf(-x);
    return __fdividef(1.0f, 1.0f + e);
}
__device__ __forceinline__ float tanhfast(float x) {
    float e = __expf(-2.0f * x);
    return __fdividef(2.0f, 1.0f + e) - 1.0f;
}
__device__ __forceinline__ float tf32_rna(float x) {
    uint32_t r;
    asm("cvt.rna.tf32.f32 %0, %1;" : "=r"(r) : "f"(x));
    return __uint_as_float(r);
}

// ---------------- recurrent scan kernel (gate-split, 384 threads) ----------------
// Grid: 128 blocks. blocks 0..63 = forward batch tiles, 64..127 = backward.
// Block: 384 threads: g = tid>>7 (gate 0..2), j = tid&127 (column).
// Thread (g,j): matmul phase -> pre-activation of gate g, column j, ALL 8 rows.
//               update phase -> owns h for column j, rows [g*3, g*3+nr).
// Dynamic smem: w_hh transposed [k=128][j=384] fp32 = 192 KB.
#define EXS 10   /* padded row stride (floats) for gate-exchange buffer */

template <int LAYER>
__global__ void __launch_bounds__(384, 1)
gru_scan(const float* __restrict__ x,
         const float* __restrict__ w_ih_f, const float* __restrict__ b_ih_f,
         const float* __restrict__ w_ih_b, const float* __restrict__ b_ih_b,
         const float* __restrict__ w_hh_f, const float* __restrict__ b_hh_f,
         const float* __restrict__ w_hh_b, const float* __restrict__ b_hh_b)
{
    extern __shared__ float wt[];                        // [k=128][jj=384] transposed w_hh
    __shared__ __align__(16) float h_s[2][HH * 8];       // [buf][col*8 + row]
    __shared__ __align__(16) float exg[3 * HH * EXS];    // gate exchange [(g*128+j)*EXS + row]

    const int bid = blockIdx.x;
    const int dir = bid >> 6;
    const int b0 = (bid & 63) * 8;
    const int tid = threadIdx.x;
    const int g = tid >> 7;          // gate 0..2
    const int j = tid & 127;         // column

    const float* w_hh = dir ? w_hh_b : w_hh_f;
    const float* b_hh = dir ? b_hh_b : b_hh_f;

    // stage w_hh transposed into smem: wt[k][jj] = w_hh[jj][k]
    for (int s = tid; s < HH * G3; s += 384) {
        int jj = s >> 7;
        int k = s & 127;
        wt[k * G3 + jj] = w_hh[s];
    }
    for (int s = tid; s < HH * 8; s += 384) h_s[0][s] = 0.0f;

    // matmul-phase constants: my gate column bias (g*128+j)
    const unsigned long long bp = pack2(b_hh[g * 128 + j]);
    const float* wcol = wt + g * 128 + j;

    // update-phase constants: rows I own, and all-3-gate input weights for column j
    const int r0 = g * 3;
    const int nr = (g == 2) ? 2 : 3;

    float wih[3][4];
    float bih[3];
    if (LAYER == 0) {
        const float* w_ih = dir ? w_ih_b : w_ih_f;
        const float* b_ihp = dir ? b_ih_b : b_ih_f;
#pragma unroll
        for (int gg = 0; gg < 3; gg++) {
            bih[gg] = b_ihp[gg * 128 + j];
#pragma unroll
            for (int f = 0; f < 4; f++) wih[gg][f] = w_ih[(gg * 128 + j) * 4 + f];
        }
    }

    float hown[3] = {0.f, 0.f, 0.f};   // h_prev for my rows (kept in regs across steps)
    __syncthreads();

    int cur = 0;
    for (int s = 0; s < TT; s++) {
        const int t = dir ? (TT - 1 - s) : s;

        // ---- prefetch xp for MY rows (consumed after the matmul; latency hidden) ----
        float xr[3], xz[3], xn[3];
        if (LAYER == 0) {
#pragma unroll
            for (int rr = 0; rr < 3; rr++) {
                if (rr < nr) {
                    int b = b0 + r0 + rr;
                    float4 xv = *(const float4*)(x + ((size_t)b * TT + t) * 4);
                    xr[rr] = bih[0] + xv.x * wih[0][0] + xv.y * wih[0][1] + xv.z * wih[0][2] + xv.w * wih[0][3];
                    xz[rr] = bih[1] + xv.x * wih[1][0] + xv.y * wih[1][1] + xv.z * wih[1][2] + xv.w * wih[1][3];
                    xn[rr] = bih[2] + xv.x * wih[2][0] + xv.y * wih[2][1] + xv.z * wih[2][2] + xv.w * wih[2][3];
                }
            }
        } else {
#pragma unroll
            for (int rr = 0; rr < 3; rr++) {
                if (rr < nr) {
                    int b = b0 + r0 + rr;
                    const float* p = &g_xp1[dir][((size_t)t * BATCH + b) * G3];
                    xr[rr] = p[j];
                    xz[rr] = p[128 + j];
                    xn[rr] = p[256 + j];
                }
            }
        }

        // ---- matmul: pre-activation of gate g, column j, rows 0..7 ----
        unsigned long long a0 = bp, a1 = bp, a2 = bp, a3 = bp;
        const float* hp = h_s[cur];
#pragma unroll 4
        for (int k = 0; k < HH; k++) {
            ulonglong2 h01 = *(const ulonglong2*)(hp + k * 8);      // rows 0-3
            ulonglong2 h23 = *(const ulonglong2*)(hp + k * 8 + 4);  // rows 4-7
            unsigned long long w = pack2(wcol[k * G3]);
            a0 = f2fma(h01.x, w, a0);
            a1 = f2fma(h01.y, w, a1);
            a2 = f2fma(h23.x, w, a2);
            a3 = f2fma(h23.y, w, a3);
        }

        // ---- exchange pre-activations ----
        {
            unsigned long long* ex = (unsigned long long*)&exg[(g * 128 + j) * EXS];
            ex[0] = a0; ex[1] = a1; ex[2] = a2; ex[3] = a3;
        }
        __syncthreads();

        // ---- h update for my rows ----
        const int nxt = cur ^ 1;
#pragma unroll
        for (int rr = 0; rr < 3; rr++) {
            if (rr < nr) {
                int row = r0 + rr;
                float gr = exg[(0 * 128 + j) * EXS + row];
                float gz = exg[(1 * 128 + j) * EXS + row];
                float gn = exg[(2 * 128 + j) * EXS + row];
                float rv = sigf(xr[rr] + gr);
                float zv = sigf(xz[rr] + gz);
                float nv = tanhfast(xn[rr] + rv * gn);
                float h = (1.0f - zv) * nv + zv * hown[rr];
                hown[rr] = h;
                h_s[nxt][j * 8 + row] = h;
                if (LAYER == 0) {
                    int b = b0 + row;
                    g_y0[((size_t)t * BATCH + b) * 256 + dir * 128 + j] = tf32_rna(h);
                }
            }
        }
        __syncthreads();
        cur = nxt;
    }

    if (LAYER == 1) {
#pragma unroll
        for (int rr = 0; rr < 3; rr++) {
            if (rr < nr) {
                int b = b0 + r0 + rr;
                g_hcat[(size_t)b * 256 + dir * 128 + j] = hown[rr];
            }
        }
    }
}

// ---------------- pre-round layer1 input weights to tf32 ----------------
__global__ void __launch_bounds__(256)
round_w_kernel(const float* __restrict__ wf, const float* __restrict__ wb)
{
    int i = blockIdx.x * 256 + threadIdx.x;
    if (i < G3 * 256) {
        g_wtf[0][i] = tf32_rna(wf[i]);
        g_wtf[1][i] = tf32_rna(wb[i]);
    }
}

// ---------------- layer-1 input-projection GEMM (tf32 tensor cores) ----------------
#define BKP 36
#define ABYTES (128 * BKP * 4)
#define BUFBYTES (2 * ABYTES)

#define CP_ASYNC_CG(dst, src) \
    asm volatile("cp.async.cg.shared.global [%0], [%1], 16;" :: "r"(dst), "l"(src))

__global__ void __launch_bounds__(256, 2)
gemm_xp1_tc(const float* __restrict__ bf, const float* __restrict__ bb)
{
    extern __shared__ float sm[];
    const int nd = blockIdx.x;              // 0..5
    const int dir = nd & 1;
    const int N0 = (nd >> 1) * 128;
    const size_t M0 = (size_t)blockIdx.y * 128;

    const float* Ag = g_y0 + M0 * 256;
    const float* Wg = &g_wtf[dir][(size_t)N0 * 256];
    const float* bias = dir ? bb : bf;

    const int tid = threadIdx.x;
    const int lane = tid & 31;
    const int wid = tid >> 5;
    const int wm = wid >> 2;
    const int wn = wid & 3;
    const int gID = lane >> 2;
    const int tig = lane & 3;

    const uint32_t smem_u = (uint32_t)__cvta_generic_to_shared(sm);

    float acc[4][4][4];
#pragma unroll
    for (int i = 0; i < 4; i++)
#pragma unroll
        for (int j2 = 0; j2 < 4; j2++)
#pragma unroll
            for (int r = 0; r < 4; r++) acc[i][j2][r] = 0.f;

#pragma unroll
    for (int v = 0; v < 4; v++) {
        int idx = v * 256 + tid;
        int m = idx >> 3, kq = idx & 7;
        uint32_t so = smem_u + (uint32_t)(m * BKP + kq * 4) * 4;
        CP_ASYNC_CG(so, Ag + (size_t)m * 256 + kq * 4);
        CP_ASYNC_CG(so + ABYTES, Wg + (size_t)m * 256 + kq * 4);
    }
    asm volatile("cp.async.commit_group;");

    for (int kc = 0; kc < 8; kc++) {
        asm volatile("cp.async.wait_group 0;");
        __syncthreads();

        if (kc < 7) {
            const int buf = (kc + 1) & 1;
            const int ko = (kc + 1) * 32;
#pragma unroll
            for (int v = 0; v < 4; v++) {
                int idx = v * 256 + tid;
                int m = idx >> 3, kq = idx & 7;
                uint32_t so = smem_u + (uint32_t)(buf * BUFBYTES) + (uint32_t)(m * BKP + kq * 4) * 4;
                CP_ASYNC_CG(so, Ag + (size_t)m * 256 + ko + kq * 4);
                CP_ASYNC_CG(so + ABYTES, Wg + (size_t)m * 256 + ko + kq * 4);
            }
            asm volatile("cp.async.commit_group;");
        }

        const float* sA = sm + (kc & 1) * (BUFBYTES / 4);
        const float* sB = sA + (ABYTES / 4);

#pragma unroll
        for (int tk = 0; tk < 4; tk++) {
            uint32_t Afr[4][4];
            uint32_t Bfr[4][2];
#pragma unroll
            for (int tm = 0; tm < 4; tm++) {
                const float* p = sA + (wm * 64 + tm * 16 + gID) * BKP + tig + tk * 8;
                Afr[tm][0] = __float_as_uint(p[0]);
                Afr[tm][1] = __float_as_uint(p[8 * BKP]);
                Afr[tm][2] = __float_as_uint(p[4]);
                Afr[tm][3] = __float_as_uint(p[8 * BKP + 4]);
            }
#pragma unroll
            for (int tn = 0; tn < 4; tn++) {
                const float* p = sB + (wn * 32 + tn * 8 + gID) * BKP + tig + tk * 8;
                Bfr[tn][0] = __float_as_uint(p[0]);
                Bfr[tn][1] = __float_as_uint(p[4]);
            }
#pragma unroll
            for (int tm = 0; tm < 4; tm++)
#pragma unroll
                for (int tn = 0; tn < 4; tn++)
                    asm volatile(
                        "mma.sync.aligned.m16n8k8.row.col.f32.tf32.tf32.f32 "
                        "{%0,%1,%2,%3}, {%4,%5,%6,%7}, {%8,%9}, {%0,%1,%2,%3};"
                        : "+f"(acc[tm][tn][0]), "+f"(acc[tm][tn][1]),
                          "+f"(acc[tm][tn][2]), "+f"(acc[tm][tn][3])
                        : "r"(Afr[tm][0]), "r"(Afr[tm][1]), "r"(Afr[tm][2]), "r"(Afr[tm][3]),
                          "r"(Bfr[tn][0]), "r"(Bfr[tn][1]));
        }
        __syncthreads();
    }

    float2 bv[4];
#pragma unroll
    for (int tn = 0; tn < 4; tn++) {
        int n = N0 + wn * 32 + tn * 8 + tig * 2;
        bv[tn].x = bias[n];
        bv[tn].y = bias[n + 1];
    }
    float* outp = &g_xp1[dir][0] + (M0 + wm * 64 + gID) * G3 + N0 + wn * 32 + tig * 2;
#pragma unroll
    for (int tm = 0; tm < 4; tm++) {
#pragma unroll
        for (int tn = 0; tn < 4; tn++) {
            float* o0 = outp + (size_t)(tm * 16) * G3 + tn * 8;
            float2 v0 = make_float2(acc[tm][tn][0] + bv[tn].x, acc[tm][tn][1] + bv[tn].y);
            float2 v1 = make_float2(acc[tm][tn][2] + bv[tn].x, acc[tm][tn][3] + bv[tn].y);
            *(float2*)o0 = v0;
            *(float2*)(o0 + 8 * G3) = v1;
        }
    }
}

// ---------------- FC head (coalesced, warp-reduce) ----------------
__global__ void __launch_bounds__(128)
head_kernel(const float* __restrict__ fc1w, const float* __restrict__ fc1b,
            const float* __restrict__ fc2w, const float* __restrict__ fc2b,
            float* __restrict__ out)
{
    __shared__ float hrow[256];
    __shared__ float a_s[128];
    const int b = blockIdx.x;
    const int tid = threadIdx.x;
    const int lane = tid & 31;
    const int wid = tid >> 5;

    hrow[tid] = g_hcat[(size_t)b * 256 + tid];
    hrow[128 + tid] = g_hcat[(size_t)b * 256 + 128 + tid];
    __syncthreads();

    for (int jj = 0; jj < 32; jj++) {
        int j = wid * 32 + jj;
        const float* wr = fc1w + (size_t)j * 256;
        float s = 0.f;
#pragma unroll
        for (int m = 0; m < 8; m++) s += hrow[lane + 32 * m] * wr[lane + 32 * m];
#pragma unroll
        for (int o = 16; o > 0; o >>= 1) s += __shfl_xor_sync(0xffffffffu, s, o);
        if (lane == 0) a_s[j] = fmaxf(s + fc1b[j], 0.f);
    }
    __syncthreads();

    if (wid < 2) {
        const float* wr = fc2w + wid * 128;
        float s = 0.f;
#pragma unroll
        for (int m = 0; m < 4; m++) s += a_s[lane + 32 * m] * wr[lane + 32 * m];
#pragma unroll
        for (int o = 16; o > 0; o >>= 1) s += __shfl_xor_sync(0xffffffffu, s, o);
        if (lane == 0) out[b * 2 + wid] = s + fc2b[wid];
    }
}

// ---------------- launch ----------------
extern "C" void kernel_launch(void* const* d_in, const int* in_sizes, int n_in,
                              void* d_out, int out_size)
{
    (void)in_sizes; (void)n_in; (void)out_size;
    const float* x        = (const float*)d_in[0];
    const float* w_ih_l0f = (const float*)d_in[1];
    const float* w_hh_l0f = (const float*)d_in[2];
    const float* b_ih_l0f = (const float*)d_in[3];
    const float* b_hh_l0f = (const float*)d_in[4];
    const float* w_ih_l0b = (const float*)d_in[5];
    const float* w_hh_l0b = (const float*)d_in[6];
    const float* b_ih_l0b = (const float*)d_in[7];
    const float* b_hh_l0b = (const float*)d_in[8];
    const float* w_ih_l1f = (const float*)d_in[9];
    const float* w_hh_l1f = (const float*)d_in[10];
    const float* b_ih_l1f = (const float*)d_in[11];
    const float* b_hh_l1f = (const float*)d_in[12];
    const float* w_ih_l1b = (const float*)d_in[13];
    const float* w_hh_l1b = (const float*)d_in[14];
    const float* b_ih_l1b = (const float*)d_in[15];
    const float* b_hh_l1b = (const float*)d_in[16];
    const float* fc1_w    = (const float*)d_in[17];
    const float* fc1_b    = (const float*)d_in[18];
    const float* fc2_w    = (const float*)d_in[19];
    const float* fc2_b    = (const float*)d_in[20];

    const int smem_scan = HH * G3 * (int)sizeof(float);  // 192 KB dynamic
    cudaFuncSetAttribute(gru_scan<0>, cudaFuncAttributeMaxDynamicSharedMemorySize, smem_scan);
    cudaFuncSetAttribute(gru_scan<1>, cudaFuncAttributeMaxDynamicSharedMemorySize, smem_scan);
    cudaFuncSetAttribute(gemm_xp1_tc, cudaFuncAttributeMaxDynamicSharedMemorySize, 2 * BUFBYTES);

    round_w_kernel<<<(G3 * 256 + 255) / 256, 256>>>(w_ih_l1f, w_ih_l1b);

    gru_scan<0><<<128, 384, smem_scan>>>(x, w_ih_l0f, b_ih_l0f, w_ih_l0b, b_ih_l0b,
                                         w_hh_l0f, b_hh_l0f, w_hh_l0b, b_hh_l0b);

    dim3 g(6, 2048, 1);
    gemm_xp1_tc<<<g, 256, 2 * BUFBYTES>>>(b_ih_l1f, b_ih_l1b);

    gru_scan<1><<<128, 384, smem_scan>>>(x, nullptr, nullptr, nullptr, nullptr,
                                         w_hh_l1f, b_hh_l1f, w_hh_l1b, b_hh_l1b);

    head_kernel<<<512, 128>>>(fc1_w, fc1_b, fc2_w, fc2_b, (float*)d_out);
}

// round 16
// speedup vs baseline: 2.7616x; 2.7616x over previous
#include <cuda_runtime.h>
#include <cuda_fp16.h>
#include <cstdint>
#include <cstddef>

#define TT 512
#define BATCH 512
#define HH 128
#define G3 384

// ---------------- scratch (static __device__, no allocation) ----------------
__device__ float g_y0[(size_t)TT * BATCH * 256];            // layer0 output [t][b][256] (fwd|bwd), tf32-rounded
__device__ float g_xp1[2][(size_t)TT * BATCH * G3];         // layer1 input projections per dir
__device__ float g_hcat[(size_t)BATCH * 256];               // final hiddens [b][256] (fwd|bwd)
__device__ float g_wtf[2][G3 * 256];                        // tf32-rounded layer1 w_ih per dir

// ---------------- helpers ----------------
__device__ __forceinline__ float sigf(float x) {
    float e = __expf(-x);
    return __fdividef(1.0f, 1.0f + e);
}
__device__ __forceinline__ float tanhfast(float x) {
    float e = __expf(-2.0f * x);
    return __fdividef(2.0f, 1.0f + e) - 1.0f;
}
__device__ __forceinline__ float tf32_rna(float x) {
    uint32_t r;
    asm("cvt.rna.tf32.f32 %0, %1;" : "=r"(r) : "f"(x));
    return __uint_as_float(r);
}

// ---------------- tensor-core recurrent scan ----------------
// Grid: 128 CTAs (64 fwd batch-tiles of 8 rows, 64 bwd). Block: 512 threads (16 warps).
// Per step: C[8 rows, 384 gates] = h[8,128] @ W[384,128]^T via fp16 mma.m16n8k16 (fp32 accum).
// Warp w owns gate columns [8w, 8w+8) for gates r/z/n (n-tiles at +0, +128, +256).
// Fragment identities (PTX m16n8k16):
//   A: a0 = A[gID][2tig,2tig+1], a2 = A[gID][2tig+8,+9]; rows 8..15 zero (a1=a3=0).
//   B: b0 = W[n0+gID][2tig,+1],  b1 = W[n0+gID][2tig+8,+9]   (W stored [n][k], k-contig).
//   C: c0,c1 = row gID, cols 2tig, 2tig+1 (rows gID+8 in c2,c3 are padding -> ignored).
// h_new computed at (gID, 8w+2tig(+1)) == exactly a half2 store into next step's A layout.
// Smem: W fp16 [384][136] (stride 136 halves -> conflict-free frag loads) + A 2x[8][136].
#define WST 136
#define WHALFS (G3 * WST)                 /* 52224 */
#define AHALFS (8 * WST)                  /* 1088  */
#define SCAN_SMEM ((WHALFS + 2 * AHALFS) * 2)   /* 108800 bytes */

#define MMA16816(c, av0, av2, bv0, bv1, zz)                                       \
    asm volatile(                                                                 \
        "mma.sync.aligned.m16n8k16.row.col.f32.f16.f16.f32 "                      \
        "{%0,%1,%2,%3}, {%4,%5,%6,%7}, {%8,%9}, {%0,%1,%2,%3};"                   \
        : "+f"(c[0]), "+f"(c[1]), "+f"(c[2]), "+f"(c[3])                          \
        : "r"(av0), "r"(zz), "r"(av2), "r"(zz), "r"(bv0), "r"(bv1))

template <int LAYER>
__global__ void __launch_bounds__(512, 1)
gru_scan_tc(const float* __restrict__ x,
            const float* __restrict__ w_ih_f, const float* __restrict__ b_ih_f,
            const float* __restrict__ w_ih_b, const float* __restrict__ b_ih_b,
            const float* __restrict__ w_hh_f, const float* __restrict__ b_hh_f,
            const float* __restrict__ w_hh_b, const float* __restrict__ b_hh_b)
{
    extern __shared__ __half sh[];
    __half* Wsh = sh;                       // [384][WST]
    __half* Abuf = sh + WHALFS;             // [2][8][WST]

    const int bid = blockIdx.x;
    const int dir = bid >> 6;
    const int b0 = (bid & 63) * 8;
    const int tid = threadIdx.x;
    const int w = tid >> 5;
    const int lane = tid & 31;
    const int gID = lane >> 2;              // row 0..7
    const int tig = lane & 3;

    const float* w_hh = dir ? w_hh_b : w_hh_f;
    const float* b_hh = dir ? b_hh_b : b_hh_f;

    // stage W (fp16) into smem: Wsh[n][k] = w_hh[n*128+k]
    for (int s = tid; s < G3 * HH; s += 512) {
        int n = s >> 7, k = s & 127;
        Wsh[n * WST + k] = __float2half_rn(w_hh[s]);
    }
    // zero both A buffers (incl. pads)
    for (int s = tid; s < 2 * AHALFS; s += 512) Abuf[s] = __ushort_as_half((unsigned short)0);

    const int j0 = w * 8 + 2 * tig;         // my two gate/h columns: j0, j0+1
    const int brow = b0 + gID;              // my batch row

    // biases for my 2 cols x 3 gates
    const float bR0 = b_hh[j0],       bR1 = b_hh[j0 + 1];
    const float bZ0 = b_hh[128 + j0], bZ1 = b_hh[128 + j0 + 1];
    const float bN0 = b_hh[256 + j0], bN1 = b_hh[256 + j0 + 1];

    // layer0 input-projection constants (2 cols x 3 gates x 4 feats)
    float wihv[3][2][4], bihv[3][2];
    if (LAYER == 0) {
        const float* w_ih = dir ? w_ih_b : w_ih_f;
        const float* b_ihp = dir ? b_ih_b : b_ih_f;
#pragma unroll
        for (int g = 0; g < 3; g++)
#pragma unroll
            for (int p = 0; p < 2; p++) {
                bihv[g][p] = b_ihp[g * 128 + j0 + p];
#pragma unroll
                for (int f = 0; f < 4; f++)
                    wihv[g][p][f] = w_ih[(g * 128 + j0 + p) * 4 + f];
            }
    }

    const __half* BrR = Wsh + (size_t)(w * 8 + gID) * WST;
    const __half* BrZ = Wsh + (size_t)(128 + w * 8 + gID) * WST;
    const __half* BrN = Wsh + (size_t)(256 + w * 8 + gID) * WST;
    const int fro = 2 * tig;                // fragment k offset within a k16 tile

    float hprev0 = 0.f, hprev1 = 0.f;
    const uint32_t zz = 0u;
    __syncthreads();

    int cur = 0;
    for (int s = 0; s < TT; s++) {
        const int t = dir ? (TT - 1 - s) : s;

        // ---- prefetch input projections (consumed after the matmul) ----
        float xr0, xr1, xz0, xz1, xn0, xn1;
        if (LAYER == 0) {
            float4 xv = *(const float4*)(x + ((size_t)brow * TT + t) * 4);
            xr0 = bihv[0][0] + xv.x * wihv[0][0][0] + xv.y * wihv[0][0][1] + xv.z * wihv[0][0][2] + xv.w * wihv[0][0][3];
            xr1 = bihv[0][1] + xv.x * wihv[0][1][0] + xv.y * wihv[0][1][1] + xv.z * wihv[0][1][2] + xv.w * wihv[0][1][3];
            xz0 = bihv[1][0] + xv.x * wihv[1][0][0] + xv.y * wihv[1][0][1] + xv.z * wihv[1][0][2] + xv.w * wihv[1][0][3];
            xz1 = bihv[1][1] + xv.x * wihv[1][1][0] + xv.y * wihv[1][1][1] + xv.z * wihv[1][1][2] + xv.w * wihv[1][1][3];
            xn0 = bihv[2][0] + xv.x * wihv[2][0][0] + xv.y * wihv[2][0][1] + xv.z * wihv[2][0][2] + xv.w * wihv[2][0][3];
            xn1 = bihv[2][1] + xv.x * wihv[2][1][0] + xv.y * wihv[2][1][1] + xv.z * wihv[2][1][2] + xv.w * wihv[2][1][3];
        } else {
            const float* p = &g_xp1[dir][((size_t)t * BATCH + brow) * G3];
            xr0 = p[j0];       xr1 = p[j0 + 1];
            xz0 = p[128 + j0]; xz1 = p[128 + j0 + 1];
            xn0 = p[256 + j0]; xn1 = p[256 + j0 + 1];
        }

        // ---- matmul: 3 accumulator sets (r,z,n), 8 k-tiles ----
        float cr[4] = {0.f, 0.f, 0.f, 0.f};
        float cz[4] = {0.f, 0.f, 0.f, 0.f};
        float cn[4] = {0.f, 0.f, 0.f, 0.f};
        const __half* Ar = Abuf + cur * AHALFS + gID * WST + fro;
#pragma unroll
        for (int kt = 0; kt < 8; kt++) {
            uint32_t a0 = *(const uint32_t*)(Ar + kt * 16);
            uint32_t a2 = *(const uint32_t*)(Ar + kt * 16 + 8);
            uint32_t br0 = *(const uint32_t*)(BrR + kt * 16 + fro);
            uint32_t br1 = *(const uint32_t*)(BrR + kt * 16 + fro + 8);
            MMA16816(cr, a0, a2, br0, br1, zz);
            uint32_t bz0 = *(const uint32_t*)(BrZ + kt * 16 + fro);
            uint32_t bz1 = *(const uint32_t*)(BrZ + kt * 16 + fro + 8);
            MMA16816(cz, a0, a2, bz0, bz1, zz);
            uint32_t bn0 = *(const uint32_t*)(BrN + kt * 16 + fro);
            uint32_t bn1 = *(const uint32_t*)(BrN + kt * 16 + fro + 8);
            MMA16816(cn, a0, a2, bn0, bn1, zz);
        }

        // ---- gates + h update (all register-local) ----
        float rv0 = sigf(xr0 + cr[0] + bR0);
        float rv1 = sigf(xr1 + cr[1] + bR1);
        float zv0 = sigf(xz0 + cz[0] + bZ0);
        float zv1 = sigf(xz1 + cz[1] + bZ1);
        float nv0 = tanhfast(xn0 + rv0 * (cn[0] + bN0));
        float nv1 = tanhfast(xn1 + rv1 * (cn[1] + bN1));
        float h0 = (1.0f - zv0) * nv0 + zv0 * hprev0;
        float h1 = (1.0f - zv1) * nv1 + zv1 * hprev1;
        hprev0 = h0; hprev1 = h1;

        // store h_new as half2 directly into next step's A-fragment slot
        __half2 hh = __floats2half2_rn(h0, h1);
        *(uint32_t*)(Abuf + (cur ^ 1) * AHALFS + gID * WST + j0) = *(uint32_t*)&hh;

        if (LAYER == 0) {
            float* yp = g_y0 + ((size_t)t * BATCH + brow) * 256 + dir * 128 + j0;
            yp[0] = tf32_rna(h0);
            yp[1] = tf32_rna(h1);
        }
        __syncthreads();
        cur ^= 1;
    }

    if (LAYER == 1) {
        float* hp = g_hcat + (size_t)brow * 256 + dir * 128 + j0;
        hp[0] = hprev0;
        hp[1] = hprev1;
    }
}

// ---------------- pre-round layer1 input weights to tf32 ----------------
__global__ void __launch_bounds__(256)
round_w_kernel(const float* __restrict__ wf, const float* __restrict__ wb)
{
    int i = blockIdx.x * 256 + threadIdx.x;
    if (i < G3 * 256) {
        g_wtf[0][i] = tf32_rna(wf[i]);
        g_wtf[1][i] = tf32_rna(wb[i]);
    }
}

// ---------------- layer-1 input-projection GEMM (tf32 tensor cores, proven R8) ----------------
#define BKP 36
#define ABYTES (128 * BKP * 4)
#define BUFBYTES (2 * ABYTES)

#define CP_ASYNC_CG(dst, src) \
    asm volatile("cp.async.cg.shared.global [%0], [%1], 16;" :: "r"(dst), "l"(src))

__global__ void __launch_bounds__(256, 2)
gemm_xp1_tc(const float* __restrict__ bf, const float* __restrict__ bb)
{
    extern __shared__ float sm[];
    const int nd = blockIdx.x;              // 0..5
    const int dir = nd & 1;
    const int N0 = (nd >> 1) * 128;
    const size_t M0 = (size_t)blockIdx.y * 128;

    const float* Ag = g_y0 + M0 * 256;
    const float* Wg = &g_wtf[dir][(size_t)N0 * 256];
    const float* bias = dir ? bb : bf;

    const int tid = threadIdx.x;
    const int lane = tid & 31;
    const int wid = tid >> 5;
    const int wm = wid >> 2;
    const int wn = wid & 3;
    const int gID = lane >> 2;
    const int tig = lane & 3;

    const uint32_t smem_u = (uint32_t)__cvta_generic_to_shared(sm);

    float acc[4][4][4];
#pragma unroll
    for (int i = 0; i < 4; i++)
#pragma unroll
        for (int j2 = 0; j2 < 4; j2++)
#pragma unroll
            for (int r = 0; r < 4; r++) acc[i][j2][r] = 0.f;

#pragma unroll
    for (int v = 0; v < 4; v++) {
        int idx = v * 256 + tid;
        int m = idx >> 3, kq = idx & 7;
        uint32_t so = smem_u + (uint32_t)(m * BKP + kq * 4) * 4;
        CP_ASYNC_CG(so, Ag + (size_t)m * 256 + kq * 4);
        CP_ASYNC_CG(so + ABYTES, Wg + (size_t)m * 256 + kq * 4);
    }
    asm volatile("cp.async.commit_group;");

    for (int kc = 0; kc < 8; kc++) {
        asm volatile("cp.async.wait_group 0;");
        __syncthreads();

        if (kc < 7) {
            const int buf = (kc + 1) & 1;
            const int ko = (kc + 1) * 32;
#pragma unroll
            for (int v = 0; v < 4; v++) {
                int idx = v * 256 + tid;
                int m = idx >> 3, kq = idx & 7;
                uint32_t so = smem_u + (uint32_t)(buf * BUFBYTES) + (uint32_t)(m * BKP + kq * 4) * 4;
                CP_ASYNC_CG(so, Ag + (size_t)m * 256 + ko + kq * 4);
                CP_ASYNC_CG(so + ABYTES, Wg + (size_t)m * 256 + ko + kq * 4);
            }
            asm volatile("cp.async.commit_group;");
        }

        const float* sA = sm + (kc & 1) * (BUFBYTES / 4);
        const float* sB = sA + (ABYTES / 4);

#pragma unroll
        for (int tk = 0; tk < 4; tk++) {
            uint32_t Afr[4][4];
            uint32_t Bfr[4][2];
#pragma unroll
            for (int tm = 0; tm < 4; tm++) {
                const float* p = sA + (wm * 64 + tm * 16 + gID) * BKP + tig + tk * 8;
                Afr[tm][0] = __float_as_uint(p[0]);
                Afr[tm][1] = __float_as_uint(p[8 * BKP]);
                Afr[tm][2] = __float_as_uint(p[4]);
                Afr[tm][3] = __float_as_uint(p[8 * BKP + 4]);
            }
#pragma unroll
            for (int tn = 0; tn < 4; tn++) {
                const float* p = sB + (wn * 32 + tn * 8 + gID) * BKP + tig + tk * 8;
                Bfr[tn][0] = __float_as_uint(p[0]);
                Bfr[tn][1] = __float_as_uint(p[4]);
            }
#pragma unroll
            for (int tm = 0; tm < 4; tm++)
#pragma unroll
                for (int tn = 0; tn < 4; tn++)
                    asm volatile(
                        "mma.sync.aligned.m16n8k8.row.col.f32.tf32.tf32.f32 "
                        "{%0,%1,%2,%3}, {%4,%5,%6,%7}, {%8,%9}, {%0,%1,%2,%3};"
                        : "+f"(acc[tm][tn][0]), "+f"(acc[tm][tn][1]),
                          "+f"(acc[tm][tn][2]), "+f"(acc[tm][tn][3])
                        : "r"(Afr[tm][0]), "r"(Afr[tm][1]), "r"(Afr[tm][2]), "r"(Afr[tm][3]),
                          "r"(Bfr[tn][0]), "r"(Bfr[tn][1]));
        }
        __syncthreads();
    }

    float2 bv[4];
#pragma unroll
    for (int tn = 0; tn < 4; tn++) {
        int n = N0 + wn * 32 + tn * 8 + tig * 2;
        bv[tn].x = bias[n];
        bv[tn].y = bias[n + 1];
    }
    float* outp = &g_xp1[dir][0] + (M0 + wm * 64 + gID) * G3 + N0 + wn * 32 + tig * 2;
#pragma unroll
    for (int tm = 0; tm < 4; tm++) {
#pragma unroll
        for (int tn = 0; tn < 4; tn++) {
            float* o0 = outp + (size_t)(tm * 16) * G3 + tn * 8;
            float2 v0 = make_float2(acc[tm][tn][0] + bv[tn].x, acc[tm][tn][1] + bv[tn].y);
            float2 v1 = make_float2(acc[tm][tn][2] + bv[tn].x, acc[tm][tn][3] + bv[tn].y);
            *(float2*)o0 = v0;
            *(float2*)(o0 + 8 * G3) = v1;
        }
    }
}

// ---------------- FC head (coalesced, warp-reduce, proven R8) ----------------
__global__ void __launch_bounds__(128)
head_kernel(const float* __restrict__ fc1w, const float* __restrict__ fc1b,
            const float* __restrict__ fc2w, const float* __restrict__ fc2b,
            float* __restrict__ out)
{
    __shared__ float hrow[256];
    __shared__ float a_s[128];
    const int b = blockIdx.x;
    const int tid = threadIdx.x;
    const int lane = tid & 31;
    const int wid = tid >> 5;

    hrow[tid] = g_hcat[(size_t)b * 256 + tid];
    hrow[128 + tid] = g_hcat[(size_t)b * 256 + 128 + tid];
    __syncthreads();

    for (int jj = 0; jj < 32; jj++) {
        int j = wid * 32 + jj;
        const float* wr = fc1w + (size_t)j * 256;
        float s = 0.f;
#pragma unroll
        for (int m = 0; m < 8; m++) s += hrow[lane + 32 * m] * wr[lane + 32 * m];
#pragma unroll
        for (int o = 16; o > 0; o >>= 1) s += __shfl_xor_sync(0xffffffffu, s, o);
        if (lane == 0) a_s[j] = fmaxf(s + fc1b[j], 0.f);
    }
    __syncthreads();

    if (wid < 2) {
        const float* wr = fc2w + wid * 128;
        float s = 0.f;
#pragma unroll
        for (int m = 0; m < 4; m++) s += a_s[lane + 32 * m] * wr[lane + 32 * m];
#pragma unroll
        for (int o = 16; o > 0; o >>= 1) s += __shfl_xor_sync(0xffffffffu, s, o);
        if (lane == 0) out[b * 2 + wid] = s + fc2b[wid];
    }
}

// ---------------- launch ----------------
extern "C" void kernel_launch(void* const* d_in, const int* in_sizes, int n_in,
                              void* d_out, int out_size)
{
    (void)in_sizes; (void)n_in; (void)out_size;
    const float* x        = (const float*)d_in[0];
    const float* w_ih_l0f = (const float*)d_in[1];
    const float* w_hh_l0f = (const float*)d_in[2];
    const float* b_ih_l0f = (const float*)d_in[3];
    const float* b_hh_l0f = (const float*)d_in[4];
    const float* w_ih_l0b = (const float*)d_in[5];
    const float* w_hh_l0b = (const float*)d_in[6];
    const float* b_ih_l0b = (const float*)d_in[7];
    const float* b_hh_l0b = (const float*)d_in[8];
    const float* w_ih_l1f = (const float*)d_in[9];
    const float* w_hh_l1f = (const float*)d_in[10];
    const float* b_ih_l1f = (const float*)d_in[11];
    const float* b_hh_l1f = (const float*)d_in[12];
    const float* w_ih_l1b = (const float*)d_in[13];
    const float* w_hh_l1b = (const float*)d_in[14];
    const float* b_ih_l1b = (const float*)d_in[15];
    const float* b_hh_l1b = (const float*)d_in[16];
    const float* fc1_w    = (const float*)d_in[17];
    const float* fc1_b    = (const float*)d_in[18];
    const float* fc2_w    = (const float*)d_in[19];
    const float* fc2_b    = (const float*)d_in[20];

    cudaFuncSetAttribute(gru_scan_tc<0>, cudaFuncAttributeMaxDynamicSharedMemorySize, SCAN_SMEM);
    cudaFuncSetAttribute(gru_scan_tc<1>, cudaFuncAttributeMaxDynamicSharedMemorySize, SCAN_SMEM);
    cudaFuncSetAttribute(gemm_xp1_tc, cudaFuncAttributeMaxDynamicSharedMemorySize, 2 * BUFBYTES);

    // pre-round layer1 input weights to tf32 (independent of scan0)
    round_w_kernel<<<(G3 * 256 + 255) / 256, 256>>>(w_ih_l1f, w_ih_l1b);

    // layer 0: fused input projection + tensor-core scan, both dirs
    gru_scan_tc<0><<<128, 512, SCAN_SMEM>>>(x, w_ih_l0f, b_ih_l0f, w_ih_l0b, b_ih_l0b,
                                            w_hh_l0f, b_hh_l0f, w_hh_l0b, b_hh_l0b);

    // layer 1 input projections on tensor cores (tf32)
    dim3 g(6, 2048, 1);
    gemm_xp1_tc<<<g, 256, 2 * BUFBYTES>>>(b_ih_l1f, b_ih_l1b);

    // layer 1 tensor-core scan
    gru_scan_tc<1><<<128, 512, SCAN_SMEM>>>(x, nullptr, nullptr, nullptr, nullptr,
                                            w_hh_l1f, b_hh_l1f, w_hh_l1b, b_hh_l1b);

    // FC head
    head_kernel<<<512, 128>>>(fc1_w, fc1_b, fc2_w, fc2_b, (float*)d_out);
}